// round 7
// baseline (speedup 1.0000x reference)
#include <cuda_runtime.h>
#include <cuda_bf16.h>

#define KB    64      // boxes
#define GRID  128     // block b handles striped rows {b, b+128, b+256, b+384}
#define TPB   1024    // 2 pixels per thread (float2)

__device__ double       g_acc[2];   // zero at load; last block resets -> zero each replay
__device__ unsigned int g_cnt;      // wraps back to 0 every run (deterministic)

__device__ __forceinline__ float sqrt_approx(float x) {
    float r; asm("sqrt.approx.f32 %0, %1;" : "=f"(r) : "f"(x)); return r;
}

__global__ __launch_bounds__(TPB) void lz_fused_kernel(
    const float* __restrict__ cm,      // center_maps (batch 0 = first 262144)
    const float* __restrict__ smap,    // scale_maps (batch 0)
    const float* __restrict__ ann,     // annotations (batch 0 = 64 float4)
    const void*  __restrict__ stridep, // stride scalar (int32 or float32)
    float* __restrict__ out)
{
    __shared__ float4 Lg[4][KB];      // per-row box record {fx1, fx2, A, C}
    __shared__ float  Ldy2[4][KB];    // per-row precomputed dy^2
    __shared__ float  Scol[4][KB];    // per-row scatter column
    __shared__ int    Sj[4][KB];      // flattened scatter index
    __shared__ float  Slh[4][KB];     // log(height)
    __shared__ int    ng[4], ns[4];
    __shared__ float  r_c[32], r_s[32];
    __shared__ int    s_last;

    const int tid  = threadIdx.x;
    const int b    = blockIdx.x;
    const int lane = tid & 31;

    // ---- phase A: warps 0..3, one warp per row; lane handles boxes {lane, lane+32}.
    if (tid < 128) {
        const int rr = tid >> 5;
        const int yr = b + (rr << 7);
        float stridef = 4.0f;
        if (stridep) {
            int iv = ((const int*)stridep)[0];
            stridef = (iv > 0 && iv <= 65536) ? (float)iv : __int_as_float(iv);
        }
        const float inv = 1.0f / stridef;
        const unsigned lt = (1u << lane) - 1u;

        int ngacc = 0, nsacc = 0;
        #pragma unroll
        for (int half = 0; half < 2; half++) {
            const int k = lane + half * 32;
            const float4 ab = ((const float4*)ann)[k];
            const int x1 = (int)floorf(ab.x * inv);
            const int y1 = (int)floorf(ab.y * inv);
            const int x2 = (int)floorf(ab.z * inv);
            const int y2 = (int)floorf(ab.w * inv);
            const int cx = (x1 + x2) >> 1, cy = (y1 + y2) >> 1;
            const float A = (float)(x1 + cx);
            const float B = (float)(y1 + cy);
            const float C = -0.5f / sqrtf((float)cx*(float)cx + (float)cy*(float)cy);
            const bool pg = (yr >= y1) && (yr < y2);
            const bool ps = ((unsigned)(yr - cy + 2)) <= 4u;
            const unsigned mg = __ballot_sync(0xffffffffu, pg);
            const unsigned ms = __ballot_sync(0xffffffffu, ps);
            if (pg) {
                const int og = ngacc + __popc(mg & lt);
                Lg[rr][og] = make_float4((float)x1, (float)x2, A, C);
                const float dy = (float)yr - B;
                Ldy2[rr][og] = dy * dy;
            }
            if (ps) {
                const int os  = nsacc + __popc(ms & lt);
                const int dyo = yr - cy;
                Scol[rr][os] = (float)(cx + dyo);
                Sj[rr][os]   = (dyo + 2) * KB + k;   // last-write-wins order
                Slh[rr][os]  = __logf((float)(y2 - y1));
            }
            ngacc += __popc(mg);
            nsacc += __popc(ms);
        }
        if (lane == 0) { ng[rr] = ngacc; ns[rr] = nsacc; }
    }
    __syncthreads();

    // ---- main pass: warp span filters FIRST; idle warps skip everything ----
    const int rmain = tid >> 8;          // which of the 4 striped rows
    const int cgrp  = tid & 255;         // float2 column group
    const int y     = b + (rmain << 7);  // striped row
    const int gq    = y * 256 + cgrp;    // float2 index into maps

    const int   x0   = cgrp << 1;
    const float fx0  = (float)x0;
    const int   wx0  = (cgrp & ~31) << 1;          // warp's first pixel x
    const float fwx0 = (float)wx0;
    const float fwxe = (float)(wx0 + 63);          // warp's last pixel x

    const int NG = ng[rmain], NS = ns[rmain];

    // span filter: NG, NS <= 64 -> at most 2 ballot chunks each
    unsigned mG[2] = {0u, 0u}, mS[2] = {0u, 0u};
    for (int h = 0; h * 32 < NG; h++) {
        const int idx = h * 32 + lane;
        bool ov = false;
        if (idx < NG) {
            const float4 bd = Lg[rmain][idx];
            ov = (fwxe >= bd.x) && (fwx0 < bd.y);
        }
        mG[h] = __ballot_sync(0xffffffffu, ov);
    }
    for (int h = 0; h * 32 < NS; h++) {
        const int idx = h * 32 + lane;
        bool ov = false;
        if (idx < NS) {
            const float c = Scol[rmain][idx];
            ov = (c >= fwx0) && (c <= fwxe);
        }
        mS[h] = __ballot_sync(0xffffffffu, ov);
    }

    float csum = 0.f, ssum = 0.f;

    if ((mG[0] | mG[1] | mS[0] | mS[1]) != 0u) {
        // this warp has real work: load map, evaluate hits only
        const float2 cm2 = ((const float2*)cm)[gq];

        float gmax[2] = {0.f,0.f};
        float blog[2] = {0.f,0.f};
        int   maxj[2] = {-1,-1};
        int   posm = 0, cenm = 0;

        #pragma unroll
        for (int h = 0; h < 2; h++) {
            unsigned m = mG[h];
            while (m) {
                const int kk = h * 32 + (__ffs(m) - 1); m &= m - 1;
                const float4 bd  = Lg[rmain][kk];      // broadcast LDS
                const float  dy2 = Ldy2[rmain][kk];
                #pragma unroll
                for (int i = 0; i < 2; i++) {
                    const float fx = fx0 + (float)i;
                    if (fx >= bd.x && fx < bd.y) {
                        posm |= (1 << i);
                        const float dx = fx - bd.z;
                        const float d  = sqrt_approx(fmaf(dx, dx, dy2));
                        gmax[i] = fmaxf(gmax[i], __expf(bd.w * d));
                    }
                }
            }
        }
        #pragma unroll
        for (int h = 0; h < 2; h++) {
            unsigned m = mS[h];
            while (m) {
                const int kk = h * 32 + (__ffs(m) - 1); m &= m - 1;
                const int t  = (int)Scol[rmain][kk] - x0;
                if ((unsigned)t <= 1u) {
                    const int j = Sj[rmain][kk];
                    if (j > maxj[t]) { maxj[t] = j; blog[t] = Slh[rmain][kk]; }
                    if (j >= 2*KB && j < 3*KB) cenm |= (1 << t);   // dyo == 0 band
                }
            }
        }

        const float pv[2] = {cm2.x, cm2.y};
        #pragma unroll
        for (int i = 0; i < 2; i++) {
            const float p = fminf(fmaxf(pv[i], 1e-4f), 0.9999f);
            if (cenm & (1 << i)) {
                const float q = 1.0f - p;
                csum += q * q * (-__logf(p));                    // ALPHA=1, GAMMA=2
            } else if (posm & (1 << i)) {
                float q = 1.0f - gmax[i];
                float w = q * q; w = w * w;                      // BETA=4
                csum += w * p * p * (-__logf(1.0f - p));
            }
            if (maxj[i] >= 0) {
                const float d = fabsf(blog[i] - smap[(size_t)gq * 2 + i]);
                ssum += (d <= 1.0f) ? 0.5f * d * d : (d - 0.5f);
            }
        }
    }

    // ---- block reduce (32 warps) ----
    #pragma unroll
    for (int off = 16; off; off >>= 1) {
        csum += __shfl_down_sync(0xffffffffu, csum, off);
        ssum += __shfl_down_sync(0xffffffffu, ssum, off);
    }
    if (lane == 0) { r_c[tid>>5] = csum; r_s[tid>>5] = ssum; }
    __syncthreads();
    if (tid < 32) {
        csum = r_c[tid]; ssum = r_s[tid];
        #pragma unroll
        for (int off = 16; off; off >>= 1) {
            csum += __shfl_down_sync(0xffffffffu, csum, off);
            ssum += __shfl_down_sync(0xffffffffu, ssum, off);
        }
    }

    // ---- global accumulate: order-insensitive double atomics, tiny tail ----
    if (tid == 0) {
        atomicAdd(&g_acc[0], (double)csum);
        atomicAdd(&g_acc[1], (double)ssum);
        __threadfence();
        unsigned old = atomicInc(&g_cnt, GRID - 1);   // wraps to 0 -> self-resetting
        s_last = (old == GRID - 1);
    }
    __syncthreads();

    if (s_last && tid == 0) {
        const double c2 = atomicAdd(&g_acc[0], 0.0);  // coherent read
        const double s2 = atomicAdd(&g_acc[1], 0.0);
        out[0] = (float)(c2 * (1.0 / 64.0));
        out[1] = (float)(s2 * (1.0 / 64.0));
        g_acc[0] = 0.0;                                // reset for next replay
        g_acc[1] = 0.0;
    }
}

extern "C" void kernel_launch(void* const* d_in, const int* in_sizes, int n_in,
                              void* d_out, int out_size) {
    const float* cm   = (const float*)d_in[0];
    const float* sm   = (const float*)d_in[1];
    const float* ann  = (const float*)d_in[2];
    const void*  strp = (n_in > 3) ? d_in[3] : nullptr;
    float* out = (float*)d_out;

    lz_fused_kernel<<<GRID, TPB>>>(cm, sm, ann, strp, out);
}

// round 8
// speedup vs baseline: 1.0182x; 1.0182x over previous
#include <cuda_runtime.h>
#include <cuda_bf16.h>

#define KB    64      // boxes
#define GRID  128     // block b handles striped rows {b, b+128, b+256, b+384}
#define TPB   1024    // 32 warps: warp w -> row (w>>3), 64-px span (w&7)

__device__ double       g_acc[2];   // zero at load; last block resets -> zero each replay
__device__ unsigned int g_cnt;      // wraps back to 0 every run (deterministic)

__device__ __forceinline__ float sqrt_approx(float x) {
    float r; asm("sqrt.approx.f32 %0, %1;" : "=f"(r) : "f"(x)); return r;
}

__global__ __launch_bounds__(TPB) void lz_fused_kernel(
    const float* __restrict__ cm,      // center_maps (batch 0 = first 262144)
    const float* __restrict__ smap,    // scale_maps (batch 0)
    const float* __restrict__ ann,     // annotations (batch 0 = 64 float4)
    const void*  __restrict__ stridep, // stride scalar (int32 or float32)
    float* __restrict__ out)
{
    __shared__ float r_c[32], r_s[32];

    const int tid  = threadIdx.x;
    const int b    = blockIdx.x;
    const int lane = tid & 31;
    const int w    = tid >> 5;          // warp 0..31
    const int rr   = w >> 3;            // which striped row
    const int sp   = w & 7;             // 64-px span within row

    const int y    = b + (rr << 7);     // this warp's row
    const int wxa  = sp << 6;           // warp first x
    const int x0   = wxa + (lane << 1); // thread's first pixel
    const float fx0 = (float)x0;
    const int   wxb = wxa + 63;

    // ---- stride (uniform tiny load) ----
    float stridef = 4.0f;
    if (stridep) {
        int iv = ((const int*)stridep)[0];
        stridef = (iv > 0 && iv <= 65536) ? (float)iv : __int_as_float(iv);
    }
    const float inv = 1.0f / stridef;

    // ---- each lane owns boxes {lane, lane+32}: predicates + ballots (no smem) ----
    const float4 ab0 = ((const float4*)ann)[lane];
    const float4 ab1 = ((const float4*)ann)[lane + 32];

    unsigned mg[2], ms[2];
    {
        // half 0
        int x1 = (int)floorf(ab0.x * inv), y1 = (int)floorf(ab0.y * inv);
        int x2 = (int)floorf(ab0.z * inv), y2 = (int)floorf(ab0.w * inv);
        int cx = (x1 + x2) >> 1, cy = (y1 + y2) >> 1, dyo = y - cy;
        bool pg = (y >= y1) && (y < y2) && (x1 <= wxb) && (x2 > wxa);
        bool ps = ((unsigned)(dyo + 2) <= 4u) && ((unsigned)(cx + dyo - wxa) <= 63u);
        mg[0] = __ballot_sync(0xffffffffu, pg);
        ms[0] = __ballot_sync(0xffffffffu, ps);
        // half 1
        x1 = (int)floorf(ab1.x * inv); y1 = (int)floorf(ab1.y * inv);
        x2 = (int)floorf(ab1.z * inv); y2 = (int)floorf(ab1.w * inv);
        cx = (x1 + x2) >> 1; cy = (y1 + y2) >> 1; dyo = y - cy;
        pg = (y >= y1) && (y < y2) && (x1 <= wxb) && (x2 > wxa);
        ps = ((unsigned)(dyo + 2) <= 4u) && ((unsigned)(cx + dyo - wxa) <= 63u);
        mg[1] = __ballot_sync(0xffffffffu, pg);
        ms[1] = __ballot_sync(0xffffffffu, ps);
    }

    float csum = 0.f, ssum = 0.f;

    if ((mg[0] | mg[1] | ms[0] | ms[1]) != 0u) {
        const int gq = y * 256 + (x0 >> 1);           // float2 index
        const float2 cm2 = ((const float2*)cm)[gq];   // issue early

        float gmax[2] = {0.f,0.f};
        float blog[2] = {0.f,0.f};
        int   maxj[2] = {-1,-1};
        int   posm = 0, cenm = 0;
        const float fy = (float)y;

        #pragma unroll
        for (int h = 0; h < 2; h++) {
            const float4 abh = h ? ab1 : ab0;
            unsigned m = mg[h];
            while (m) {
                const int src = __ffs(m) - 1; m &= m - 1;
                // broadcast raw annotation, recompute params locally
                const float a0 = __shfl_sync(0xffffffffu, abh.x, src);
                const float a1 = __shfl_sync(0xffffffffu, abh.y, src);
                const float a2 = __shfl_sync(0xffffffffu, abh.z, src);
                const float a3 = __shfl_sync(0xffffffffu, abh.w, src);
                const int x1 = (int)floorf(a0 * inv), y1 = (int)floorf(a1 * inv);
                const int x2 = (int)floorf(a2 * inv), y2 = (int)floorf(a3 * inv);
                const int cx = (x1 + x2) >> 1, cy = (y1 + y2) >> 1;
                const float A = (float)(x1 + cx);
                const float C = -0.5f / sqrt_approx((float)cx*(float)cx + (float)cy*(float)cy);
                const float dy = fy - (float)(y1 + cy);
                const float dy2 = dy * dy;
                const float fx1 = (float)x1, fx2 = (float)x2;
                #pragma unroll
                for (int i = 0; i < 2; i++) {
                    const float fx = fx0 + (float)i;
                    if (fx >= fx1 && fx < fx2) {
                        posm |= (1 << i);
                        const float dx = fx - A;
                        const float d  = sqrt_approx(fmaf(dx, dx, dy2));
                        gmax[i] = fmaxf(gmax[i], __expf(C * d));
                    }
                }
            }
            m = ms[h];
            while (m) {
                const int src = __ffs(m) - 1; m &= m - 1;
                const float a0 = __shfl_sync(0xffffffffu, abh.x, src);
                const float a1 = __shfl_sync(0xffffffffu, abh.y, src);
                const float a2 = __shfl_sync(0xffffffffu, abh.z, src);
                const float a3 = __shfl_sync(0xffffffffu, abh.w, src);
                const int x1 = (int)floorf(a0 * inv), y1 = (int)floorf(a1 * inv);
                const int x2 = (int)floorf(a2 * inv), y2 = (int)floorf(a3 * inv);
                const int cx = (x1 + x2) >> 1, cy = (y1 + y2) >> 1;
                const int dyo = y - cy;
                const int t = cx + dyo - x0;
                if ((unsigned)t <= 1u) {
                    const int k = src + (h << 5);
                    const int j = (dyo + 2) * KB + k;       // last-write-wins order
                    if (j > maxj[t]) { maxj[t] = j; blog[t] = __logf((float)(y2 - y1)); }
                    if (dyo == 0) cenm |= (1 << t);
                }
            }
        }

        const float pv[2] = {cm2.x, cm2.y};
        #pragma unroll
        for (int i = 0; i < 2; i++) {
            const float p = fminf(fmaxf(pv[i], 1e-4f), 0.9999f);
            if (cenm & (1 << i)) {
                const float q = 1.0f - p;
                csum += q * q * (-__logf(p));                    // ALPHA=1, GAMMA=2
            } else if (posm & (1 << i)) {
                float q = 1.0f - gmax[i];
                float wgt = q * q; wgt = wgt * wgt;              // BETA=4
                csum += wgt * p * p * (-__logf(1.0f - p));
            }
            if (maxj[i] >= 0) {
                const float d = fabsf(blog[i] - smap[(size_t)gq * 2 + i]);
                ssum += (d <= 1.0f) ? 0.5f * d * d : (d - 0.5f);
            }
        }
    }

    // ---- block reduce (single barrier) ----
    #pragma unroll
    for (int off = 16; off; off >>= 1) {
        csum += __shfl_down_sync(0xffffffffu, csum, off);
        ssum += __shfl_down_sync(0xffffffffu, ssum, off);
    }
    if (lane == 0) { r_c[w] = csum; r_s[w] = ssum; }
    __syncthreads();
    if (tid < 32) {
        csum = r_c[tid]; ssum = r_s[tid];
        #pragma unroll
        for (int off = 16; off; off >>= 1) {
            csum += __shfl_down_sync(0xffffffffu, csum, off);
            ssum += __shfl_down_sync(0xffffffffu, ssum, off);
        }
        if (tid == 0) {
            atomicAdd(&g_acc[0], (double)csum);
            atomicAdd(&g_acc[1], (double)ssum);
            __threadfence();
            unsigned old = atomicInc(&g_cnt, GRID - 1);   // wraps to 0 -> self-resetting
            if (old == GRID - 1) {
                const double c2 = atomicAdd(&g_acc[0], 0.0);  // coherent read
                const double s2 = atomicAdd(&g_acc[1], 0.0);
                out[0] = (float)(c2 * (1.0 / 64.0));
                out[1] = (float)(s2 * (1.0 / 64.0));
                g_acc[0] = 0.0;                                // reset for next replay
                g_acc[1] = 0.0;
            }
        }
    }
}

extern "C" void kernel_launch(void* const* d_in, const int* in_sizes, int n_in,
                              void* d_out, int out_size) {
    const float* cm   = (const float*)d_in[0];
    const float* sm   = (const float*)d_in[1];
    const float* ann  = (const float*)d_in[2];
    const void*  strp = (n_in > 3) ? d_in[3] : nullptr;
    float* out = (float*)d_out;

    lz_fused_kernel<<<GRID, TPB>>>(cm, sm, ann, strp, out);
}